// round 4
// baseline (speedup 1.0000x reference)
#include <cuda_runtime.h>
#include <cstdint>

#define B_TOTAL 65536
#define HALF_B  32768
#define TLEN 200
#define DIN 6
#define HID 50
#define NSTEP 101
#define TPB 64

typedef unsigned long long u64;

// Scratch for pooled initial state (static __device__ global: allocation-free).
__device__ float g_y0[B_TOTAL * DIN];

// ---------------- f32x2 helpers (FFMA2 only reachable via PTX) ----------------
__device__ __forceinline__ u64 pack_dup(float v) {
    u64 r; asm("mov.b64 %0, {%1, %2};" : "=l"(r) : "f"(v), "f"(v)); return r;
}
__device__ __forceinline__ u64 pack2f(float a, float b) {
    u64 r; asm("mov.b64 %0, {%1, %2};" : "=l"(r) : "f"(a), "f"(b)); return r;
}
__device__ __forceinline__ void unpack2(u64 v, float& lo, float& hi) {
    asm("mov.b64 {%0, %1}, %2;" : "=f"(lo), "=f"(hi) : "l"(v));
}
__device__ __forceinline__ u64 ffma2(u64 a, u64 b, u64 c) {
    u64 d; asm("fma.rn.f32x2 %0, %1, %2, %3;" : "=l"(d) : "l"(a), "l"(b), "l"(c)); return d;
}
__device__ __forceinline__ unsigned smem_addr(const void* p) {
    return (unsigned)__cvta_generic_to_shared(p);
}
__device__ __forceinline__ void lds2(unsigned a, u64& x, u64& y) {
    asm("ld.shared.v2.u64 {%0, %1}, [%2];" : "=l"(x), "=l"(y) : "r"(a));
}
__device__ __forceinline__ u64 lds1(unsigned a) {
    u64 x; asm("ld.shared.u64 %0, [%1];" : "=l"(x) : "r"(a)); return x;
}
__device__ __forceinline__ void sts2(unsigned a, u64 x, u64 y) {
    asm volatile("st.shared.v2.u64 [%0], {%1, %2};" :: "r"(a), "l"(x), "l"(y));
}

struct SAddrs { unsigned w1, b1, w2, b2, w3, b3, h; };

// ---------------- MLP dynamics for a PAIR of samples ----------------
// Weights in shared (rows padded: W1/W2 stride 52 floats, W3 stride 8).
// Every broadcast weight load feeds both samples (2x FFMA2 per 16B delivered).
__device__ __forceinline__ void mlp2(const float* ytA, const float* ytB,
                                     float* kA, float* kB, const SAddrs s) {
    // ---- layer 1 (both samples, shared weight stream), park ReLU(h1) ----
    {
        u64 hA[25], hB[25];
        {
            unsigned a = s.b1;
            #pragma unroll
            for (int p = 0; p < 12; p++) lds2(a + 16 * p, hA[2 * p], hA[2 * p + 1]);
            hA[24] = lds1(a + 192);
            #pragma unroll
            for (int i = 0; i < 25; i++) hB[i] = hA[i];
        }
        #pragma unroll
        for (int d = 0; d < DIN; d++) {
            u64 da = pack_dup(ytA[d]);
            u64 db = pack_dup(ytB[d]);
            unsigned r = s.w1 + d * 208;
            #pragma unroll
            for (int p = 0; p < 12; p++) {
                u64 w0, w1;
                lds2(r + 16 * p, w0, w1);
                hA[2 * p]     = ffma2(da, w0, hA[2 * p]);
                hA[2 * p + 1] = ffma2(da, w1, hA[2 * p + 1]);
                hB[2 * p]     = ffma2(db, w0, hB[2 * p]);
                hB[2 * p + 1] = ffma2(db, w1, hB[2 * p + 1]);
            }
            u64 wl = lds1(r + 192);
            hA[24] = ffma2(da, wl, hA[24]);
            hB[24] = ffma2(db, wl, hB[24]);
        }
        #pragma unroll
        for (int q = 0; q < 25; q++) {
            float a0, a1, b0, b1;
            unpack2(hA[q], a0, a1);
            unpack2(hB[q], b0, b1);
            sts2(s.h + (unsigned)q * (TPB * 16u),
                 pack2f(fmaxf(a0, 0.0f), fmaxf(a1, 0.0f)),
                 pack2f(fmaxf(b0, 0.0f), fmaxf(b1, 0.0f)));
        }
    }

    // ---- layer 2: h2 = ReLU(h1 @ W2 + b2), both h2 sets in regs ----
    u64 gA[25], gB[25];
    {
        unsigned a = s.b2;
        #pragma unroll
        for (int p = 0; p < 12; p++) lds2(a + 16 * p, gA[2 * p], gA[2 * p + 1]);
        gA[24] = lds1(a + 192);
        #pragma unroll
        for (int i = 0; i < 25; i++) gB[i] = gA[i];
    }
    #pragma unroll 1
    for (int q = 0; q < 25; q++) {
        u64 pa, pb;
        lds2(s.h + (unsigned)q * (TPB * 16u), pa, pb);
        float a0, a1, b0, b1;
        unpack2(pa, a0, a1);
        unpack2(pb, b0, b1);
        u64 dA0 = pack_dup(a0), dA1 = pack_dup(a1);
        u64 dB0 = pack_dup(b0), dB1 = pack_dup(b1);
        unsigned r0 = s.w2 + (2 * q) * 208;
        unsigned r1 = r0 + 208;
        #pragma unroll
        for (int p = 0; p < 12; p++) {
            u64 w0, w1;
            lds2(r0 + 16 * p, w0, w1);
            gA[2 * p]     = ffma2(dA0, w0, gA[2 * p]);
            gA[2 * p + 1] = ffma2(dA0, w1, gA[2 * p + 1]);
            gB[2 * p]     = ffma2(dB0, w0, gB[2 * p]);
            gB[2 * p + 1] = ffma2(dB0, w1, gB[2 * p + 1]);
        }
        {
            u64 wl = lds1(r0 + 192);
            gA[24] = ffma2(dA0, wl, gA[24]);
            gB[24] = ffma2(dB0, wl, gB[24]);
        }
        #pragma unroll
        for (int p = 0; p < 12; p++) {
            u64 w0, w1;
            lds2(r1 + 16 * p, w0, w1);
            gA[2 * p]     = ffma2(dA1, w0, gA[2 * p]);
            gA[2 * p + 1] = ffma2(dA1, w1, gA[2 * p + 1]);
            gB[2 * p]     = ffma2(dB1, w0, gB[2 * p]);
            gB[2 * p + 1] = ffma2(dB1, w1, gB[2 * p + 1]);
        }
        {
            u64 wl = lds1(r1 + 192);
            gA[24] = ffma2(dA1, wl, gA[24]);
            gB[24] = ffma2(dB1, wl, gB[24]);
        }
    }

    // ---- layer 3: k = ReLU(h2) @ W3 + b3 (both samples) ----
    u64 oA0, oA1, oA2, oB0, oB1, oB2;
    lds2(s.b3, oA0, oA1);
    oA2 = lds1(s.b3 + 16);
    oB0 = oA0; oB1 = oA1; oB2 = oA2;
    #pragma unroll 1
    for (int q = 0; q < 25; q++) {
        float a0, a1, b0, b1;
        unpack2(gA[q], a0, a1);
        unpack2(gB[q], b0, b1);
        u64 dA0 = pack_dup(fmaxf(a0, 0.0f)), dA1 = pack_dup(fmaxf(a1, 0.0f));
        u64 dB0 = pack_dup(fmaxf(b0, 0.0f)), dB1 = pack_dup(fmaxf(b1, 0.0f));
        unsigned r0 = s.w3 + (2 * q) * 32;
        u64 w0, w1, wl;
        lds2(r0, w0, w1);
        wl = lds1(r0 + 16);
        oA0 = ffma2(dA0, w0, oA0); oA1 = ffma2(dA0, w1, oA1); oA2 = ffma2(dA0, wl, oA2);
        oB0 = ffma2(dB0, w0, oB0); oB1 = ffma2(dB0, w1, oB1); oB2 = ffma2(dB0, wl, oB2);
        lds2(r0 + 32, w0, w1);
        wl = lds1(r0 + 48);
        oA0 = ffma2(dA1, w0, oA0); oA1 = ffma2(dA1, w1, oA1); oA2 = ffma2(dA1, wl, oA2);
        oB0 = ffma2(dB1, w0, oB0); oB1 = ffma2(dB1, w1, oB1); oB2 = ffma2(dB1, wl, oB2);
    }
    unpack2(oA0, kA[0], kA[1]); unpack2(oA1, kA[2], kA[3]); unpack2(oA2, kA[4], kA[5]);
    unpack2(oB0, kB[0], kB[1]); unpack2(oB1, kB[2], kB[3]); unpack2(oB2, kB[4], kB[5]);
}

// ---------------- Phase A: y0 = mean over T (warp per sample) ----------------
__global__ void mean_kernel(const float* __restrict__ x0) {
    const unsigned w = (blockIdx.x * blockDim.x + threadIdx.x) >> 5;
    const int lane = threadIdx.x & 31;
    if (w >= B_TOTAL) return;
    const float2* p = reinterpret_cast<const float2*>(x0) + (size_t)w * 600u;
    float sx = 0.0f, sy = 0.0f;
    if (lane < 30) {
        #pragma unroll
        for (int kk = 0; kk < 20; kk++) {
            float2 v = __ldg(p + lane + 30 * kk);
            sx += v.x;
            sy += v.y;
        }
    }
    const int c = lane % 3;
    float v0 = (c == 0) ? sx : 0.0f, v1 = (c == 0) ? sy : 0.0f;
    float v2 = (c == 1) ? sx : 0.0f, v3 = (c == 1) ? sy : 0.0f;
    float v4 = (c == 2) ? sx : 0.0f, v5 = (c == 2) ? sy : 0.0f;
    #pragma unroll
    for (int o = 16; o; o >>= 1) {
        v0 += __shfl_xor_sync(0xffffffffu, v0, o);
        v1 += __shfl_xor_sync(0xffffffffu, v1, o);
        v2 += __shfl_xor_sync(0xffffffffu, v2, o);
        v3 += __shfl_xor_sync(0xffffffffu, v3, o);
        v4 += __shfl_xor_sync(0xffffffffu, v4, o);
        v5 += __shfl_xor_sync(0xffffffffu, v5, o);
    }
    if (lane == 0) {
        const float inv = 1.0f / (float)TLEN;
        float* o = g_y0 + (size_t)w * 6u;
        o[0] = v0 * inv; o[1] = v1 * inv; o[2] = v2 * inv;
        o[3] = v3 * inv; o[4] = v4 * inv; o[5] = v5 * inv;
    }
}

// ---------------- Phase B: RK4, TWO samples per thread ----------------
__global__ void __launch_bounds__(TPB, 5) ode_kernel(
    const float* __restrict__ t_span,
    const float* __restrict__ W1, const float* __restrict__ b1,
    const float* __restrict__ W2, const float* __restrict__ b2,
    const float* __restrict__ W3, const float* __restrict__ b3,
    float* __restrict__ out) {
    __shared__ __align__(16) float sW1[DIN * 52];
    __shared__ __align__(16) float sW2[HID * 52];
    __shared__ __align__(16) float sW3[HID * 8];
    __shared__ __align__(16) float sB1[52];
    __shared__ __align__(16) float sB2[52];
    __shared__ __align__(16) float sB3[8];
    __shared__ __align__(16) float sTs[NSTEP + 1];
    // Per-thread slab: [q][tid] holding 16B = {h1A pair, h1B pair}.
    __shared__ __align__(16) u64 sH[25 * TPB * 2];

    const int t = threadIdx.x;
    for (int i = t; i < DIN * HID; i += TPB) sW1[(i / HID) * 52 + (i % HID)] = W1[i];
    for (int i = t; i < HID * HID; i += TPB) sW2[(i / HID) * 52 + (i % HID)] = W2[i];
    for (int i = t; i < HID * DIN; i += TPB) sW3[(i / DIN) * 8 + (i % DIN)] = W3[i];
    if (t < HID) { sB1[t] = b1[t]; sB2[t] = b2[t]; }
    if (t < DIN) sB3[t] = b3[t];
    for (int i = t; i < NSTEP + 1; i += TPB) sTs[i] = t_span[i];
    __syncthreads();

    SAddrs s;
    s.w1 = smem_addr(sW1); s.b1 = smem_addr(sB1);
    s.w2 = smem_addr(sW2); s.b2 = smem_addr(sB2);
    s.w3 = smem_addr(sW3); s.b3 = smem_addr(sB3);
    s.h  = smem_addr(sH) + (unsigned)t * 16u;

    const int gid = blockIdx.x * TPB + t;   // sample A = gid, sample B = gid + 32768
    float yA[6], yB[6];
    #pragma unroll
    for (int d = 0; d < 6; d++) {
        yA[d] = g_y0[gid * 6 + d];
        yB[d] = g_y0[(gid + HALF_B) * 6 + d];
    }

    float ytA[6], ytB[6], kA[6], kB[6], accA[6], accB[6];

    #pragma unroll 1
    for (int stp = 0; stp < NSTEP; stp++) {
        const float dt = sTs[stp + 1] - sTs[stp];
        #pragma unroll
        for (int d = 0; d < 6; d++) { ytA[d] = yA[d]; ytB[d] = yB[d]; }
        #pragma unroll 1
        for (int st = 0; st < 4; st++) {
            mlp2(ytA, ytB, kA, kB, s);
            if (st == 0) {
                #pragma unroll
                for (int d = 0; d < 6; d++) {
                    accA[d] = kA[d]; ytA[d] = fmaf(0.5f * dt, kA[d], yA[d]);
                    accB[d] = kB[d]; ytB[d] = fmaf(0.5f * dt, kB[d], yB[d]);
                }
            } else if (st == 1) {
                #pragma unroll
                for (int d = 0; d < 6; d++) {
                    accA[d] += 2.0f * kA[d]; ytA[d] = fmaf(0.5f * dt, kA[d], yA[d]);
                    accB[d] += 2.0f * kB[d]; ytB[d] = fmaf(0.5f * dt, kB[d], yB[d]);
                }
            } else if (st == 2) {
                #pragma unroll
                for (int d = 0; d < 6; d++) {
                    accA[d] += 2.0f * kA[d]; ytA[d] = fmaf(dt, kA[d], yA[d]);
                    accB[d] += 2.0f * kB[d]; ytB[d] = fmaf(dt, kB[d], yB[d]);
                }
            } else {
                #pragma unroll
                for (int d = 0; d < 6; d++) {
                    yA[d] = fmaf(dt * (1.0f / 6.0f), accA[d] + kA[d], yA[d]);
                    yB[d] = fmaf(dt * (1.0f / 6.0f), accB[d] + kB[d], yB[d]);
                }
            }
        }
    }

    #pragma unroll
    for (int d = 0; d < 6; d++) {
        out[gid * 6 + d] = yA[d];
        out[(gid + HALF_B) * 6 + d] = yB[d];
    }
}

extern "C" void kernel_launch(void* const* d_in, const int* in_sizes, int n_in,
                              void* d_out, int out_size) {
    const float* x0 = (const float*)d_in[0];
    const float* ts = (const float*)d_in[1];
    const float* W1 = (const float*)d_in[2];
    const float* b1 = (const float*)d_in[3];
    const float* W2 = (const float*)d_in[4];
    const float* b2 = (const float*)d_in[5];
    const float* W3 = (const float*)d_in[6];
    const float* b3 = (const float*)d_in[7];
    float* out = (float*)d_out;

    mean_kernel<<<8192, 256>>>(x0);
    ode_kernel<<<HALF_B / TPB, TPB>>>(ts, W1, b1, W2, b2, W3, b3, out);
}